// round 13
// baseline (speedup 1.0000x reference)
#include <cuda_runtime.h>
#include <cstdint>

// Tensor-train contraction, B=262144, D=32 binary cores, R=16.
// out[b] = v0(x0) @ M1..M30(x) @ w31(x31)
//
// Tables:
//   A: UA[lo8] = (v0@M1@M2@M3)[lo&15] @ (M4..M7)[lo>>4]     (256 x 16)
//      WA[e8]  = (M24..M27)[e&15] @ (M28@M29@M30@w31)[e>>4] (256 x 16)
//   B (per block, inline product doubling):
//      U[(hi<<8)|lo] = UA[lo] @ (M8..M11)[hi&15] @ (M12..M15)[hi>>4]
//      W[(hi<<8)|lo] = (M16..M19)[lo&15] @ (M20..M23)[lo>>4] @ WA[hi]
//   idx: pack X rows into 32-bit masks (ballot)
//   gather: out[b] = dot(U[pa], W[ps]), 4 lanes cooperate per batch
//
// Graph: fork -> {A -> B} on s2  ||  {idx} on main -> join -> gather.

__device__ __align__(128) float g_UA[256 * 16];
__device__ __align__(128) float g_WA[256 * 16];
__device__ __align__(128) float g_U[65536 * 16];
__device__ __align__(128) float g_W[65536 * 16];
__device__ __align__(128) unsigned g_idx[262144];

// cores_mid M_j (j=1..30): float2 cm2[(j-1)*256 + r*16 + s] = {bit0, bit1}
// core_first [0][r][bit] at cf[r*2+bit];  core_last [r][0][bit] at cl[r*2+bit]

// Grid 32 x 256: blk 0..15 UA (sel=blk), blk 16..31 WA (sel=blk-16).
__global__ __launch_bounds__(256) void tt_A(const float* __restrict__ cf,
                                            const float* __restrict__ cm,
                                            const float* __restrict__ cl) {
    __shared__ float sm[3648];
    const float2* cm2 = reinterpret_cast<const float2*>(cm);
    int blk = blockIdx.x;
    int tid = threadIdx.x;

    bool isU = blk < 16;
    int sel = isU ? blk : blk - 16;           // TU/TW combo index
    float* Mv = sm;                           // [jj][bit][s*16+r], 1536
    float* Msel = sm + 1536;                  // [jl][row*16+col], 1024
    float* V = sm + 2560;                     // ping-pong 2 x 272
    float* P = sm + 3104;                     // ping-pong 2 x 272

    // vector-chain matrices (both bit variants)
    for (int idx = tid; idx < 768; idx += 256) {
        int jj = idx >> 8;
        int rs = idx & 255;
        if (isU) {
            float2 v2 = cm2[jj * 256 + rs];          // M_{jj+1}[s][r], rs=s*16+r
            Mv[jj * 512 + rs] = v2.x;
            Mv[jj * 512 + 256 + rs] = v2.y;
        } else {
            int rr = rs >> 4, ss = rs & 15;
            float2 v2 = cm2[(29 - jj) * 256 + rs];   // M_{30-jj}[rr][ss]
            Mv[jj * 512 + ss * 16 + rr] = v2.x;
            Mv[jj * 512 + 256 + ss * 16 + rr] = v2.y;
        }
    }
    // selected TU/TW matrices
#pragma unroll
    for (int jl = 0; jl < 4; jl++) {
        float2 v2 = cm2[((isU ? 3 : 23) + jl) * 256 + tid];
        Msel[jl * 256 + tid] = ((sel >> jl) & 1) ? v2.y : v2.x;
    }
    int e = tid >> 4, r = tid & 15;
    V[e * 17 + r] = isU ? cf[r * 2 + (e & 1)] : cl[r * 2 + ((e >> 3) & 1)];
    P[e * 17 + r] = Msel[3 * 256 + tid];
    __syncthreads();

    int cur = 0;
    for (int jj = 0; jj < 3; jj++) {
        int bit = isU ? ((e >> (jj + 1)) & 1) : ((e >> (2 - jj)) & 1);
        const float* M = &Mv[jj * 512 + bit * 256];
        float a = 0.f;
#pragma unroll
        for (int s = 0; s < 16; s++) a += V[cur * 272 + e * 17 + s] * M[s * 16 + r];
        int jl = 2 - jj;
        float b = 0.f;
#pragma unroll
        for (int s = 0; s < 16; s++)
            b += Msel[jl * 256 + e * 16 + s] * P[cur * 272 + s * 17 + r];
        V[(cur ^ 1) * 272 + e * 17 + r] = a;
        P[(cur ^ 1) * 272 + e * 17 + r] = b;
        __syncthreads();
        cur ^= 1;
    }
    if (isU) {
        // UA[sel*16+e][r] = sum_s uv4[e][s] * TU[s][r]
        float a = 0.f;
#pragma unroll
        for (int s = 0; s < 16; s++)
            a += V[cur * 272 + e * 17 + s] * P[cur * 272 + s * 17 + r];
        g_UA[(sel * 16 + e) * 16 + r] = a;
    } else {
        // WA[e*16+sel][r] = sum_s TW[r][s] * wv4[e][s]
        float a = 0.f;
#pragma unroll
        for (int s = 0; s < 16; s++)
            a += P[cur * 272 + r * 17 + s] * V[cur * 272 + e * 17 + s];
        g_WA[(e * 16 + sel) * 16 + r] = a;
    }
}

// Grid 512 x 256: blk<256 -> U side (hi=blk), else W side (lo=blk-256).
// Builds its own 8-matrix product via doubling, then combines with UA/WA.
__global__ __launch_bounds__(256) void tt_B(const float* __restrict__ cm) {
    __shared__ float Ms[2048];                 // 8 selected matrices [k][r*16+c]
    __shared__ float Pp[4][256];               // pair products
    __shared__ float Qq[2][256];               // quad products
    __shared__ __align__(16) float Pm[256];    // full 8-product
    const float2* cm2 = reinterpret_cast<const float2*>(cm);
    int blk = blockIdx.x;
    int t = threadIdx.x;
    int r = t >> 4, c = t & 15;
    const float4* PmV = reinterpret_cast<const float4*>(Pm);

    bool isU = blk < 256;
    int e8 = isU ? blk : blk - 256;            // 8-bit selector (hi for U, lo for W)
    int jb = isU ? 7 : 15;                     // cm2 block of M8 / M16

    // load 8 selected matrices: Ms[k] = M_{(isU?8:16)+k} with bit k of e8
#pragma unroll
    for (int k = 0; k < 8; k++) {
        float2 v2 = cm2[(jb + k) * 256 + t];
        Ms[k * 256 + t] = ((e8 >> k) & 1) ? v2.y : v2.x;
    }
    __syncthreads();

    // doubling step 1: 4 pair products (4 outputs/thread)
#pragma unroll
    for (int q = 0; q < 4; q++) {
        float a = 0.f;
#pragma unroll
        for (int s = 0; s < 16; s++)
            a += Ms[(2 * q) * 256 + r * 16 + s] * Ms[(2 * q + 1) * 256 + s * 16 + c];
        Pp[q][t] = a;
    }
    __syncthreads();
    // step 2: 2 quad products
#pragma unroll
    for (int h = 0; h < 2; h++) {
        float a = 0.f;
#pragma unroll
        for (int s = 0; s < 16; s++)
            a += Pp[2 * h][r * 16 + s] * Pp[2 * h + 1][s * 16 + c];
        Qq[h][t] = a;
    }
    __syncthreads();
    // step 3: full product Pm[r][c]
    {
        float a = 0.f;
#pragma unroll
        for (int s = 0; s < 16; s++)
            a += Qq[0][r * 16 + s] * Qq[1][s * 16 + c];
        Pm[t] = a;
    }
    __syncthreads();

    if (isU) {
        // U[(hi<<8)|lo][s] = sum_r UA[lo][r] * Pm[r][s];  lo = t
        int hi = e8, lo = t;
        const float4* uap = reinterpret_cast<const float4*>(&g_UA[lo * 16]);
        float u[16];
#pragma unroll
        for (int k = 0; k < 4; k++) {
            float4 q = uap[k];
            u[4 * k] = q.x; u[4 * k + 1] = q.y; u[4 * k + 2] = q.z; u[4 * k + 3] = q.w;
        }
        float res[16];
#pragma unroll
        for (int s = 0; s < 16; s++) res[s] = 0.f;
#pragma unroll
        for (int rr = 0; rr < 16; rr++) {
            float4 m0 = PmV[rr * 4 + 0], m1 = PmV[rr * 4 + 1];
            float4 m2 = PmV[rr * 4 + 2], m3 = PmV[rr * 4 + 3];
            float ur = u[rr];
            res[0] += ur * m0.x;  res[1] += ur * m0.y;  res[2] += ur * m0.z;  res[3] += ur * m0.w;
            res[4] += ur * m1.x;  res[5] += ur * m1.y;  res[6] += ur * m1.z;  res[7] += ur * m1.w;
            res[8] += ur * m2.x;  res[9] += ur * m2.y;  res[10] += ur * m2.z; res[11] += ur * m2.w;
            res[12] += ur * m3.x; res[13] += ur * m3.y; res[14] += ur * m3.z; res[15] += ur * m3.w;
        }
        float4* dstv = reinterpret_cast<float4*>(&g_U[(((unsigned)hi << 8) | lo) * 16]);
#pragma unroll
        for (int k = 0; k < 4; k++)
            dstv[k] = make_float4(res[4 * k], res[4 * k + 1], res[4 * k + 2], res[4 * k + 3]);
    } else {
        // W[(hi<<8)|lo][r] = sum_s Pm[r][s] * WA[hi][s];  hi = t
        int lo = e8, hi = t;
        const float4* wap = reinterpret_cast<const float4*>(&g_WA[hi * 16]);
        float4 w0 = wap[0], w1 = wap[1], w2 = wap[2], w3 = wap[3];
        float res[16];
#pragma unroll
        for (int rr = 0; rr < 16; rr++) {
            float4 m0 = PmV[rr * 4 + 0], m1 = PmV[rr * 4 + 1];
            float4 m2 = PmV[rr * 4 + 2], m3 = PmV[rr * 4 + 3];
            float a = m0.x * w0.x + m0.y * w0.y + m0.z * w0.z + m0.w * w0.w;
            a += m1.x * w1.x + m1.y * w1.y + m1.z * w1.z + m1.w * w1.w;
            a += m2.x * w2.x + m2.y * w2.y + m2.z * w2.z + m2.w * w2.w;
            a += m3.x * w3.x + m3.y * w3.y + m3.z * w3.z + m3.w * w3.w;
            res[rr] = a;
        }
        float4* dstv = reinterpret_cast<float4*>(&g_W[(((unsigned)hi << 8) | lo) * 16]);
#pragma unroll
        for (int k = 0; k < 4; k++)
            dstv[k] = make_float4(res[4 * k], res[4 * k + 1], res[4 * k + 2], res[4 * k + 3]);
    }
}

// Pack X rows into 32-bit masks. Warp covers 32 batches; lane l loads X[b_i,l]
// (coalesced 128B per iter); ballot packs the index; lane i keeps batch i's mask.
__global__ __launch_bounds__(256) void tt_idx(const int* __restrict__ X) {
    int warpId = blockIdx.x * (blockDim.x >> 5) + (threadIdx.x >> 5);
    int lane = threadIdx.x & 31;
    size_t base = (size_t)warpId * 32 * 32;
    unsigned m = 0;
#pragma unroll
    for (int i = 0; i < 32; i++) {
        int x = X[base + (size_t)i * 32 + lane];
        unsigned bm = __ballot_sync(0xFFFFFFFFu, x != 0);
        if (i == lane) m = bm;
    }
    g_idx[warpId * 32 + lane] = m;
}

// 4 lanes cooperate per batch: lane j loads float4 j of U and W; 8 batches per
// pass, 4 passes. Gather lines/instr: 8 instead of 32.
__global__ __launch_bounds__(256) void tt_gather(float* __restrict__ out) {
    int warpId = blockIdx.x * (blockDim.x >> 5) + (threadIdx.x >> 5);
    int lane = threadIdx.x & 31;
    unsigned m = g_idx[warpId * 32 + lane];

    const float4* U4 = reinterpret_cast<const float4*>(g_U);
    const float4* W4 = reinterpret_cast<const float4*>(g_W);
    int j = lane & 3;
    int bq = lane >> 2;

    unsigned pa[4], ps[4];
#pragma unroll
    for (int p = 0; p < 4; p++) {
        unsigned mm = __shfl_sync(0xFFFFFFFFu, m, p * 8 + bq);
        pa[p] = mm & 0xFFFFu;
        ps[p] = mm >> 16;
    }
    float4 uu[4], ww[4];
#pragma unroll
    for (int p = 0; p < 4; p++) {
        uu[p] = U4[pa[p] * 4 + j];
        ww[p] = W4[ps[p] * 4 + j];
    }
#pragma unroll
    for (int p = 0; p < 4; p++) {
        float4 u = uu[p], w = ww[p];
        float pd = u.x * w.x + u.y * w.y + u.z * w.z + u.w * w.w;
        pd += __shfl_xor_sync(0xFFFFFFFFu, pd, 1);
        pd += __shfl_xor_sync(0xFFFFFFFFu, pd, 2);
        if (j == 0) out[warpId * 32 + p * 8 + bq] = pd;
    }
}

extern "C" void kernel_launch(void* const* d_in, const int* in_sizes, int n_in,
                              void* d_out, int out_size) {
    const int* X = (const int*)d_in[0];
    const float* cf = (const float*)d_in[1];
    const float* cm = (const float*)d_in[2];
    const float* cl = (const float*)d_in[3];
    float* out = (float*)d_out;

    // One-time side-stream + fork/join events (created outside graph capture;
    // kernel_launch itself is only called for correctness + capture, so this
    // never allocates inside the graph).
    static cudaStream_t s2 = nullptr;
    static cudaEvent_t evFork = nullptr, evJoin = nullptr;
    if (s2 == nullptr) {
        cudaStreamCreateWithFlags(&s2, cudaStreamNonBlocking);
        cudaEventCreateWithFlags(&evFork, cudaEventDisableTiming);
        cudaEventCreateWithFlags(&evJoin, cudaEventDisableTiming);
    }

    int nBlocks = out_size / 256;  // 1024

    // fork: table pipeline (A -> B) on s2, X indexing on the main stream
    cudaEventRecord(evFork, (cudaStream_t)0);
    cudaStreamWaitEvent(s2, evFork, 0);
    tt_A<<<32, 256, 0, s2>>>(cf, cm, cl);
    tt_B<<<512, 256, 0, s2>>>(cm);
    cudaEventRecord(evJoin, s2);

    tt_idx<<<nBlocks, 256>>>(X);

    // join, then gather
    cudaStreamWaitEvent((cudaStream_t)0, evJoin, 0);
    tt_gather<<<nBlocks, 256>>>(out);
}